// round 13
// baseline (speedup 1.0000x reference)
#include <cuda_runtime.h>

// Problem constants
#define B_DIM 8
#define C_DIM 1024
#define T_DIM 1024
#define H_DIM 8
#define DQK   128
#define DFC1  128

// ---------------------------------------------------------------------------
// Scratch (device globals: allocation-free rule)
// ---------------------------------------------------------------------------
__device__ float g_W1v[H_DIM * DFC1 * C_DIM];          // W1 @ Wv[h]      (4 MB)
__device__ float g_c1 [H_DIM * DFC1];                  // gamma*W1@bv + b1
__device__ float g_q  [B_DIM * H_DIM * DQK  * T_DIM];  // 32 MB
__device__ float g_k  [B_DIM * H_DIM * DQK  * T_DIM];  // 32 MB
__device__ float g_u  [B_DIM * H_DIM * DFC1 * T_DIM];  // 32 MB
__device__ float g_xw1[B_DIM * DFC1 * T_DIM];          // 4 MB

// ---------------------------------------------------------------------------
// Generic tiled SGEMM: C[z] (128 x 1024) = A (128 x 1024) * B[z] (1024 x 1024)
//   A offset = sA * (z % 8), B offset = sB * (z / bdiv), C offset = z*128*1024
//   optional bias per output row: bias + 128*(z%8)
// Block: 256 threads, tile 128x128, BK=16, 8x8 microtile.
// ---------------------------------------------------------------------------
__global__ __launch_bounds__(256) void sgemm128(
    const float* __restrict__ A, long sA,
    const float* __restrict__ B, long sB, int bdiv,
    float* __restrict__ Cmat,
    const float* __restrict__ bias)
{
    int z = blockIdx.z;
    const float* Ab = A + sA * (long)(z & 7);
    const float* Bb = B + sB * (long)(z / bdiv);
    float* Cb = Cmat + (long)z * (128 * 1024);
    const float* biasb = bias ? (bias + (z & 7) * 128) : nullptr;

    __shared__ float As[16 * 128];   // As[kk][m]
    __shared__ float Bs[16 * 128];   // Bs[kk][n]

    int tid = threadIdx.x;
    int tx = tid & 15, ty = tid >> 4;
    int colBase = blockIdx.x * 128;

    float acc[8][8];
#pragma unroll
    for (int i = 0; i < 8; i++)
#pragma unroll
        for (int j = 0; j < 8; j++) acc[i][j] = 0.f;

    for (int k0 = 0; k0 < 1024; k0 += 16) {
#pragma unroll
        for (int i = 0; i < 8; i++) {
            int idx = tid + i * 256;
            int m = idx >> 4, kk = idx & 15;
            As[kk * 128 + m] = Ab[m * 1024 + k0 + kk];
        }
#pragma unroll
        for (int i = 0; i < 8; i++) {
            int idx = tid + i * 256;
            int kk = idx >> 7, n = idx & 127;
            Bs[kk * 128 + n] = Bb[(k0 + kk) * 1024 + colBase + n];
        }
        __syncthreads();

#pragma unroll
        for (int kk = 0; kk < 16; kk++) {
            float4 a0 = *(const float4*)&As[kk * 128 + ty * 8];
            float4 a1 = *(const float4*)&As[kk * 128 + ty * 8 + 4];
            float4 b0 = *(const float4*)&Bs[kk * 128 + tx * 8];
            float4 b1 = *(const float4*)&Bs[kk * 128 + tx * 8 + 4];
            float ar[8] = {a0.x, a0.y, a0.z, a0.w, a1.x, a1.y, a1.z, a1.w};
            float br[8] = {b0.x, b0.y, b0.z, b0.w, b1.x, b1.y, b1.z, b1.w};
#pragma unroll
            for (int i = 0; i < 8; i++)
#pragma unroll
                for (int j = 0; j < 8; j++) acc[i][j] += ar[i] * br[j];
        }
        __syncthreads();
    }

#pragma unroll
    for (int i = 0; i < 8; i++) {
        int m = ty * 8 + i;
        float bb = biasb ? biasb[m] : 0.f;
        float4 v0 = make_float4(acc[i][0] + bb, acc[i][1] + bb, acc[i][2] + bb, acc[i][3] + bb);
        float4 v1 = make_float4(acc[i][4] + bb, acc[i][5] + bb, acc[i][6] + bb, acc[i][7] + bb);
        *(float4*)&Cb[m * 1024 + colBase + tx * 8]     = v0;
        *(float4*)&Cb[m * 1024 + colBase + tx * 8 + 4] = v1;
    }
}

// ---------------------------------------------------------------------------
// c1[h][f] = gamma[h] * sum_c W1[f][c]*bv[h][c] + b1[f]
// ---------------------------------------------------------------------------
__global__ void c1_kernel(const float* __restrict__ W1, const float* __restrict__ bv,
                          const float* __restrict__ b1, const float* __restrict__ gamma,
                          float* __restrict__ c1)
{
    int h = blockIdx.x, f = threadIdx.x;
    const float* bvh = bv + h * 1024;
    float s = 0.f;
    for (int c = 0; c < 1024; c++) s += W1[f * 1024 + c] * bvh[c];
    c1[h * 128 + f] = gamma[h] * s + b1[f];
}

// ---------------------------------------------------------------------------
// Fused flash attention + FC1 epilogue + FC2 + residual + output permute.
// Per block: one (b,h), 64 query rows. Online softmax over s-chunks of 64.
//   z[f,t] = sum_s u[f,s]*P[t,s]; y1 = relu(gamma*z + xw1 + c1);
//   y2 = relu(W2@y1 + b2); out[b, d*8+h, t] = y2[d] + x[b, d*8+h, t]
// Threads 256 as 16x16; GEMM1 micro 4x4 (q x s), GEMM2/3 micro 4x8 (q x f/d).
// ---------------------------------------------------------------------------
#define SMEM_FLOATS 29120
#define SMEM_BYTES  (SMEM_FLOATS * 4)

__global__ __launch_bounds__(256) void attn_fused(
    const float* __restrict__ qg, const float* __restrict__ kg,
    const float* __restrict__ ug, const float* __restrict__ xw1,
    const float* __restrict__ c1, const float* __restrict__ gamma,
    const float* __restrict__ W2, const float* __restrict__ b2,
    const float* __restrict__ x,  float* __restrict__ out)
{
    extern __shared__ float sm[];
    float* Qs   = sm;             // [128][64]      8192
    float* Ks   = sm + 8192;      // [128][64]      8192
    float* Us   = sm + 16384;     // [128][65]      8320
    float* Ss   = sm + 24704;     // [64][66]       4224
    float* m_sm = sm + 28928;     // [64]
    float* f_sm = m_sm + 64;      // [64]
    float* l_sm = f_sm + 64;      // [64]
    // epilogue aliases (overlap Qs/Ks/Us/Ss; l_sm region untouched)
    float* W2s = sm;              // [128][129]     16512  (W2s[f][d])
    float* y1s = sm + 16512;      // [64][132]      8448

    int tid = threadIdx.x;
    int tx = tid & 15, ty = tid >> 4;
    int qt = blockIdx.x;          // 0..15
    int h  = blockIdx.y;
    int b  = blockIdx.z;
    int bh = b * 8 + h;
    int t0 = qt * 64;

    const float* qb = qg + (long)bh * 128 * 1024;
    const float* kb = kg + (long)bh * 128 * 1024;
    const float* ub = ug + (long)bh * 128 * 1024;

    // Load Q tile: Qs[c][q]
    for (int i = tid; i < 128 * 64; i += 256) {
        int c = i >> 6, qq = i & 63;
        Qs[c * 64 + qq] = qb[c * 1024 + t0 + qq];
    }
    if (tid < 64) { m_sm[tid] = -1e30f; l_sm[tid] = 0.f; }
    __syncthreads();

    float acc2[4][8];
#pragma unroll
    for (int i = 0; i < 4; i++)
#pragma unroll
        for (int j = 0; j < 8; j++) acc2[i][j] = 0.f;

    for (int s0 = 0; s0 < 1024; s0 += 64) {
        // load K, U chunks
        for (int i = tid; i < 128 * 64; i += 256) {
            int c = i >> 6, ss = i & 63;
            Ks[c * 64 + ss] = kb[c * 1024 + s0 + ss];
            Us[c * 65 + ss] = ub[c * 1024 + s0 + ss];
        }
        __syncthreads();

        // GEMM1: S[q][s] = sum_c Q[c][q] K[c][s]
        float a1[16];
#pragma unroll
        for (int i = 0; i < 16; i++) a1[i] = 0.f;
#pragma unroll 8
        for (int c = 0; c < 128; c++) {
            float4 av = *(const float4*)&Qs[c * 64 + ty * 4];
            float4 kv = *(const float4*)&Ks[c * 64 + tx * 4];
            float ar[4] = {av.x, av.y, av.z, av.w};
            float br[4] = {kv.x, kv.y, kv.z, kv.w};
#pragma unroll
            for (int i = 0; i < 4; i++)
#pragma unroll
                for (int j = 0; j < 4; j++) a1[i * 4 + j] += ar[i] * br[j];
        }

        // chunk row-max (reduce across the 16 tx lanes; same ty = 16 contiguous lanes)
        float cm[4];
#pragma unroll
        for (int i = 0; i < 4; i++) {
            float m = a1[i * 4];
#pragma unroll
            for (int j = 1; j < 4; j++) m = fmaxf(m, a1[i * 4 + j]);
            cm[i] = m;
        }
#pragma unroll
        for (int o = 1; o < 16; o <<= 1)
#pragma unroll
            for (int i = 0; i < 4; i++)
                cm[i] = fmaxf(cm[i], __shfl_xor_sync(0xffffffffu, cm[i], o));

        if (tx == 0) {
#pragma unroll
            for (int i = 0; i < 4; i++) {
                int r = ty * 4 + i;
                float mo = m_sm[r];
                float mn = fmaxf(mo, cm[i]);
                m_sm[r] = mn;
                f_sm[r] = __expf(mo - mn);
            }
        }
        __syncthreads();

        // P = exp(S - m), row sums, rescale accumulators
        float ps[4];
#pragma unroll
        for (int i = 0; i < 4; i++) {
            int r = ty * 4 + i;
            float mn = m_sm[r];
            float s = 0.f;
#pragma unroll
            for (int j = 0; j < 4; j++) {
                float p = __expf(a1[i * 4 + j] - mn);
                Ss[r * 66 + tx * 4 + j] = p;
                s += p;
            }
            ps[i] = s;
        }
#pragma unroll
        for (int o = 1; o < 16; o <<= 1)
#pragma unroll
            for (int i = 0; i < 4; i++)
                ps[i] += __shfl_xor_sync(0xffffffffu, ps[i], o);

        float fc[4];
#pragma unroll
        for (int i = 0; i < 4; i++) fc[i] = f_sm[ty * 4 + i];
        if (tx == 0) {
#pragma unroll
            for (int i = 0; i < 4; i++) {
                int r = ty * 4 + i;
                l_sm[r] = l_sm[r] * fc[i] + ps[i];
            }
        }
#pragma unroll
        for (int i = 0; i < 4; i++)
#pragma unroll
            for (int j = 0; j < 8; j++) acc2[i][j] *= fc[i];
        __syncthreads();

        // GEMM2: acc2[q][f] += sum_s P[q][s] * U[f][s]
#pragma unroll 4
        for (int s = 0; s < 64; s++) {
            float ar[4], br[8];
#pragma unroll
            for (int i = 0; i < 4; i++) ar[i] = Ss[(ty * 4 + i) * 66 + s];
#pragma unroll
            for (int j = 0; j < 8; j++) br[j] = Us[(tx * 8 + j) * 65 + s];
#pragma unroll
            for (int i = 0; i < 4; i++)
#pragma unroll
                for (int j = 0; j < 8; j++) acc2[i][j] += ar[i] * br[j];
        }
        __syncthreads();
    }

    // ------------- epilogue: y1 = relu(gamma*z + xw1 + c1) -------------
    float linv[4];
#pragma unroll
    for (int i = 0; i < 4; i++) linv[i] = 1.f / l_sm[ty * 4 + i];
    float gam = __ldg(&gamma[h]);

#pragma unroll
    for (int i = 0; i < 4; i++) {
        int r = ty * 4 + i;
        int t = t0 + r;
#pragma unroll
        for (int j = 0; j < 8; j++) {
            int f = tx * 8 + j;
            float z = acc2[i][j] * linv[i];
            float y = gam * z + __ldg(&xw1[((long)b * 128 + f) * 1024 + t])
                              + __ldg(&c1[h * 128 + f]);
            y1s[r * 132 + f] = fmaxf(y, 0.f);
        }
    }
    // load W2 transposed into smem: W2s[f][d]
    for (int i2 = tid; i2 < 128 * 128; i2 += 256) {
        int d = i2 >> 7, f = i2 & 127;
        W2s[f * 129 + d] = W2[i2];
    }
    __syncthreads();

    // GEMM3: y2[q][d] = sum_f y1[q][f] * W2[d][f]
    float a3[4][8];
#pragma unroll
    for (int i = 0; i < 4; i++)
#pragma unroll
        for (int j = 0; j < 8; j++) a3[i][j] = 0.f;
#pragma unroll 4
    for (int f = 0; f < 128; f++) {
        float ar[4], br[8];
#pragma unroll
        for (int i = 0; i < 4; i++) ar[i] = y1s[(ty * 4 + i) * 132 + f];
#pragma unroll
        for (int j = 0; j < 8; j++) br[j] = W2s[f * 129 + tx * 8 + j];
#pragma unroll
        for (int i = 0; i < 4; i++)
#pragma unroll
            for (int j = 0; j < 8; j++) a3[i][j] += ar[i] * br[j];
    }

    // out[b, d*8+h, t] = relu(y2 + b2) + x[b, d*8+h, t]
#pragma unroll
    for (int j = 0; j < 8; j++) {
        int d = tx * 8 + j;
        int cch = d * 8 + h;
        long base = ((long)b * 1024 + cch) * 1024 + t0 + ty * 4;
        float bb = __ldg(&b2[d]);
        float4 xv = *(const float4*)&x[base];
        float4 ov;
        ov.x = fmaxf(a3[0][j] + bb, 0.f) + xv.x;
        ov.y = fmaxf(a3[1][j] + bb, 0.f) + xv.y;
        ov.z = fmaxf(a3[2][j] + bb, 0.f) + xv.z;
        ov.w = fmaxf(a3[3][j] + bb, 0.f) + xv.w;
        *(float4*)&out[base] = ov;
    }
}

// ---------------------------------------------------------------------------
extern "C" void kernel_launch(void* const* d_in, const int* in_sizes, int n_in,
                              void* d_out, int out_size)
{
    (void)in_sizes; (void)n_in; (void)out_size;
    const float* x     = (const float*)d_in[0];
    const float* Wq    = (const float*)d_in[1];
    const float* bq    = (const float*)d_in[2];
    const float* Wk    = (const float*)d_in[3];
    const float* bk    = (const float*)d_in[4];
    const float* Wv    = (const float*)d_in[5];
    const float* bv    = (const float*)d_in[6];
    const float* gamma = (const float*)d_in[7];
    const float* W1    = (const float*)d_in[8];
    const float* b1    = (const float*)d_in[9];
    const float* W2    = (const float*)d_in[10];
    const float* b2    = (const float*)d_in[11];
    float* out = (float*)d_out;

    float *pW1v, *pc1, *pq, *pk, *pu, *pxw1;
    cudaGetSymbolAddress((void**)&pW1v, g_W1v);
    cudaGetSymbolAddress((void**)&pc1,  g_c1);
    cudaGetSymbolAddress((void**)&pq,   g_q);
    cudaGetSymbolAddress((void**)&pk,   g_k);
    cudaGetSymbolAddress((void**)&pu,   g_u);
    cudaGetSymbolAddress((void**)&pxw1, g_xw1);

    cudaFuncSetAttribute(attn_fused, cudaFuncAttributeMaxDynamicSharedMemorySize, SMEM_BYTES);

    dim3 blk(256);
    // W1v[h] = W1 @ Wv[h]
    sgemm128<<<dim3(8, 1, 8),  blk>>>(W1, 0, Wv, (long)C_DIM * C_DIM, 1, pW1v, nullptr);
    // c1[h] = gamma*W1@bv + b1
    c1_kernel<<<8, 128>>>(W1, bv, b1, gamma, pc1);
    // q, k, u, xw1 projections
    sgemm128<<<dim3(8, 1, 64), blk>>>(Wq,   (long)DQK  * C_DIM, x, (long)C_DIM * T_DIM, 8, pq,   bq);
    sgemm128<<<dim3(8, 1, 64), blk>>>(Wk,   (long)DQK  * C_DIM, x, (long)C_DIM * T_DIM, 8, pk,   bk);
    sgemm128<<<dim3(8, 1, 64), blk>>>(pW1v, (long)DFC1 * C_DIM, x, (long)C_DIM * T_DIM, 8, pu,   nullptr);
    sgemm128<<<dim3(8, 1, 8),  blk>>>(W1, 0,                    x, (long)C_DIM * T_DIM, 1, pxw1, nullptr);
    // fused flash attention + MLP + residual
    attn_fused<<<dim3(16, 8, 8), blk, SMEM_BYTES>>>(pq, pk, pu, pxw1, pc1, gamma, W2, b2, x, out);
}

// round 14
// speedup vs baseline: 1.0064x; 1.0064x over previous
#include <cuda_runtime.h>

// Problem constants
#define B_DIM 8
#define C_DIM 1024
#define T_DIM 1024
#define H_DIM 8
#define DQK   128
#define DFC1  128

// ---------------------------------------------------------------------------
// Scratch (device globals: allocation-free rule)
// ---------------------------------------------------------------------------
__device__ float g_W1v[H_DIM * DFC1 * C_DIM];          // W1 @ Wv[h]      (4 MB)
__device__ float g_c1 [H_DIM * DFC1];                  // gamma*W1@bv + b1
__device__ float g_q  [B_DIM * H_DIM * DQK  * T_DIM];  // 32 MB
__device__ float g_k  [B_DIM * H_DIM * DQK  * T_DIM];  // 32 MB
__device__ float g_u  [B_DIM * H_DIM * DFC1 * T_DIM];  // 32 MB
__device__ float g_xw1[B_DIM * DFC1 * T_DIM];          // 4 MB

// ---------------------------------------------------------------------------
// Generic tiled SGEMM: C[z] (128 x 1024) = A (128 x 1024) * B[z] (1024 x 1024)
//   A offset = sA * (z % 8), B offset = sB * (z / bdiv), C offset = z*128*1024
//   optional bias per output row: bias + 128*(z%8)
// Block: 256 threads, tile 128x128, BK=16, 8x8 microtile.
// ---------------------------------------------------------------------------
__global__ __launch_bounds__(256) void sgemm128(
    const float* __restrict__ A, long sA,
    const float* __restrict__ B, long sB, int bdiv,
    float* __restrict__ Cmat,
    const float* __restrict__ bias)
{
    int z = blockIdx.z;
    const float* Ab = A + sA * (long)(z & 7);
    const float* Bb = B + sB * (long)(z / bdiv);
    float* Cb = Cmat + (long)z * (128 * 1024);
    const float* biasb = bias ? (bias + (z & 7) * 128) : nullptr;

    __shared__ float As[16 * 128];   // As[kk][m]
    __shared__ float Bs[16 * 128];   // Bs[kk][n]

    int tid = threadIdx.x;
    int tx = tid & 15, ty = tid >> 4;
    int colBase = blockIdx.x * 128;

    float acc[8][8];
#pragma unroll
    for (int i = 0; i < 8; i++)
#pragma unroll
        for (int j = 0; j < 8; j++) acc[i][j] = 0.f;

    for (int k0 = 0; k0 < 1024; k0 += 16) {
#pragma unroll
        for (int i = 0; i < 8; i++) {
            int idx = tid + i * 256;
            int m = idx >> 4, kk = idx & 15;
            As[kk * 128 + m] = Ab[m * 1024 + k0 + kk];
        }
#pragma unroll
        for (int i = 0; i < 8; i++) {
            int idx = tid + i * 256;
            int kk = idx >> 7, n = idx & 127;
            Bs[kk * 128 + n] = Bb[(k0 + kk) * 1024 + colBase + n];
        }
        __syncthreads();

#pragma unroll
        for (int kk = 0; kk < 16; kk++) {
            float4 a0 = *(const float4*)&As[kk * 128 + ty * 8];
            float4 a1 = *(const float4*)&As[kk * 128 + ty * 8 + 4];
            float4 b0 = *(const float4*)&Bs[kk * 128 + tx * 8];
            float4 b1 = *(const float4*)&Bs[kk * 128 + tx * 8 + 4];
            float ar[8] = {a0.x, a0.y, a0.z, a0.w, a1.x, a1.y, a1.z, a1.w};
            float br[8] = {b0.x, b0.y, b0.z, b0.w, b1.x, b1.y, b1.z, b1.w};
#pragma unroll
            for (int i = 0; i < 8; i++)
#pragma unroll
                for (int j = 0; j < 8; j++) acc[i][j] += ar[i] * br[j];
        }
        __syncthreads();
    }

#pragma unroll
    for (int i = 0; i < 8; i++) {
        int m = ty * 8 + i;
        float bb = biasb ? biasb[m] : 0.f;
        float4 v0 = make_float4(acc[i][0] + bb, acc[i][1] + bb, acc[i][2] + bb, acc[i][3] + bb);
        float4 v1 = make_float4(acc[i][4] + bb, acc[i][5] + bb, acc[i][6] + bb, acc[i][7] + bb);
        *(float4*)&Cb[m * 1024 + colBase + tx * 8]     = v0;
        *(float4*)&Cb[m * 1024 + colBase + tx * 8 + 4] = v1;
    }
}

// ---------------------------------------------------------------------------
// c1[h][f] = gamma[h] * sum_c W1[f][c]*bv[h][c] + b1[f]
// ---------------------------------------------------------------------------
__global__ void c1_kernel(const float* __restrict__ W1, const float* __restrict__ bv,
                          const float* __restrict__ b1, const float* __restrict__ gamma,
                          float* __restrict__ c1)
{
    int h = blockIdx.x, f = threadIdx.x;
    const float* bvh = bv + h * 1024;
    float s = 0.f;
    for (int c = 0; c < 1024; c++) s += W1[f * 1024 + c] * bvh[c];
    c1[h * 128 + f] = gamma[h] * s + b1[f];
}

// ---------------------------------------------------------------------------
// Fused flash attention + FC1 epilogue + FC2 + residual + output permute.
// Per block: one (b,h), 64 query rows. Online softmax over s-chunks of 64.
//   z[f,t] = sum_s u[f,s]*P[t,s]; y1 = relu(gamma*z + xw1 + c1);
//   y2 = relu(W2@y1 + b2); out[b, d*8+h, t] = y2[d] + x[b, d*8+h, t]
// Threads 256 as 16x16; GEMM1 micro 4x4 (q x s), GEMM2/3 micro 4x8 (q x f/d).
// ---------------------------------------------------------------------------
#define SMEM_FLOATS 29120
#define SMEM_BYTES  (SMEM_FLOATS * 4)

__global__ __launch_bounds__(256) void attn_fused(
    const float* __restrict__ qg, const float* __restrict__ kg,
    const float* __restrict__ ug, const float* __restrict__ xw1,
    const float* __restrict__ c1, const float* __restrict__ gamma,
    const float* __restrict__ W2, const float* __restrict__ b2,
    const float* __restrict__ x,  float* __restrict__ out)
{
    extern __shared__ float sm[];
    float* Qs   = sm;             // [128][64]      8192
    float* Ks   = sm + 8192;      // [128][64]      8192
    float* Us   = sm + 16384;     // [128][65]      8320
    float* Ss   = sm + 24704;     // [64][66]       4224
    float* m_sm = sm + 28928;     // [64]
    float* f_sm = m_sm + 64;      // [64]
    float* l_sm = f_sm + 64;      // [64]
    // epilogue aliases (overlap Qs/Ks/Us/Ss; l_sm region untouched)
    float* W2s = sm;              // [128][129]     16512  (W2s[f][d])
    float* y1s = sm + 16512;      // [64][132]      8448

    int tid = threadIdx.x;
    int tx = tid & 15, ty = tid >> 4;
    int qt = blockIdx.x;          // 0..15
    int h  = blockIdx.y;
    int b  = blockIdx.z;
    int bh = b * 8 + h;
    int t0 = qt * 64;

    const float* qb = qg + (long)bh * 128 * 1024;
    const float* kb = kg + (long)bh * 128 * 1024;
    const float* ub = ug + (long)bh * 128 * 1024;

    // Load Q tile: Qs[c][q]
    for (int i = tid; i < 128 * 64; i += 256) {
        int c = i >> 6, qq = i & 63;
        Qs[c * 64 + qq] = qb[c * 1024 + t0 + qq];
    }
    if (tid < 64) { m_sm[tid] = -1e30f; l_sm[tid] = 0.f; }
    __syncthreads();

    float acc2[4][8];
#pragma unroll
    for (int i = 0; i < 4; i++)
#pragma unroll
        for (int j = 0; j < 8; j++) acc2[i][j] = 0.f;

    for (int s0 = 0; s0 < 1024; s0 += 64) {
        // load K, U chunks
        for (int i = tid; i < 128 * 64; i += 256) {
            int c = i >> 6, ss = i & 63;
            Ks[c * 64 + ss] = kb[c * 1024 + s0 + ss];
            Us[c * 65 + ss] = ub[c * 1024 + s0 + ss];
        }
        __syncthreads();

        // GEMM1: S[q][s] = sum_c Q[c][q] K[c][s]
        float a1[16];
#pragma unroll
        for (int i = 0; i < 16; i++) a1[i] = 0.f;
#pragma unroll 8
        for (int c = 0; c < 128; c++) {
            float4 av = *(const float4*)&Qs[c * 64 + ty * 4];
            float4 kv = *(const float4*)&Ks[c * 64 + tx * 4];
            float ar[4] = {av.x, av.y, av.z, av.w};
            float br[4] = {kv.x, kv.y, kv.z, kv.w};
#pragma unroll
            for (int i = 0; i < 4; i++)
#pragma unroll
                for (int j = 0; j < 4; j++) a1[i * 4 + j] += ar[i] * br[j];
        }

        // chunk row-max (reduce across the 16 tx lanes; same ty = 16 contiguous lanes)
        float cm[4];
#pragma unroll
        for (int i = 0; i < 4; i++) {
            float m = a1[i * 4];
#pragma unroll
            for (int j = 1; j < 4; j++) m = fmaxf(m, a1[i * 4 + j]);
            cm[i] = m;
        }
#pragma unroll
        for (int o = 1; o < 16; o <<= 1)
#pragma unroll
            for (int i = 0; i < 4; i++)
                cm[i] = fmaxf(cm[i], __shfl_xor_sync(0xffffffffu, cm[i], o));

        if (tx == 0) {
#pragma unroll
            for (int i = 0; i < 4; i++) {
                int r = ty * 4 + i;
                float mo = m_sm[r];
                float mn = fmaxf(mo, cm[i]);
                m_sm[r] = mn;
                f_sm[r] = __expf(mo - mn);
            }
        }
        __syncthreads();

        // P = exp(S - m), row sums, rescale accumulators
        float ps[4];
#pragma unroll
        for (int i = 0; i < 4; i++) {
            int r = ty * 4 + i;
            float mn = m_sm[r];
            float s = 0.f;
#pragma unroll
            for (int j = 0; j < 4; j++) {
                float p = __expf(a1[i * 4 + j] - mn);
                Ss[r * 66 + tx * 4 + j] = p;
                s += p;
            }
            ps[i] = s;
        }
#pragma unroll
        for (int o = 1; o < 16; o <<= 1)
#pragma unroll
            for (int i = 0; i < 4; i++)
                ps[i] += __shfl_xor_sync(0xffffffffu, ps[i], o);

        float fc[4];
#pragma unroll
        for (int i = 0; i < 4; i++) fc[i] = f_sm[ty * 4 + i];
        if (tx == 0) {
#pragma unroll
            for (int i = 0; i < 4; i++) {
                int r = ty * 4 + i;
                l_sm[r] = l_sm[r] * fc[i] + ps[i];
            }
        }
#pragma unroll
        for (int i = 0; i < 4; i++)
#pragma unroll
            for (int j = 0; j < 8; j++) acc2[i][j] *= fc[i];
        __syncthreads();

        // GEMM2: acc2[q][f] += sum_s P[q][s] * U[f][s]
#pragma unroll 4
        for (int s = 0; s < 64; s++) {
            float ar[4], br[8];
#pragma unroll
            for (int i = 0; i < 4; i++) ar[i] = Ss[(ty * 4 + i) * 66 + s];
#pragma unroll
            for (int j = 0; j < 8; j++) br[j] = Us[(tx * 8 + j) * 65 + s];
#pragma unroll
            for (int i = 0; i < 4; i++)
#pragma unroll
                for (int j = 0; j < 8; j++) acc2[i][j] += ar[i] * br[j];
        }
        __syncthreads();
    }

    // ------------- epilogue: y1 = relu(gamma*z + xw1 + c1) -------------
    float linv[4];
#pragma unroll
    for (int i = 0; i < 4; i++) linv[i] = 1.f / l_sm[ty * 4 + i];
    float gam = __ldg(&gamma[h]);

#pragma unroll
    for (int i = 0; i < 4; i++) {
        int r = ty * 4 + i;
        int t = t0 + r;
#pragma unroll
        for (int j = 0; j < 8; j++) {
            int f = tx * 8 + j;
            float z = acc2[i][j] * linv[i];
            float y = gam * z + __ldg(&xw1[((long)b * 128 + f) * 1024 + t])
                              + __ldg(&c1[h * 128 + f]);
            y1s[r * 132 + f] = fmaxf(y, 0.f);
        }
    }
    // load W2 transposed into smem: W2s[f][d]
    for (int i2 = tid; i2 < 128 * 128; i2 += 256) {
        int d = i2 >> 7, f = i2 & 127;
        W2s[f * 129 + d] = W2[i2];
    }
    __syncthreads();

    // GEMM3: y2[q][d] = sum_f y1[q][f] * W2[d][f]
    float a3[4][8];
#pragma unroll
    for (int i = 0; i < 4; i++)
#pragma unroll
        for (int j = 0; j < 8; j++) a3[i][j] = 0.f;
#pragma unroll 4
    for (int f = 0; f < 128; f++) {
        float ar[4], br[8];
#pragma unroll
        for (int i = 0; i < 4; i++) ar[i] = y1s[(ty * 4 + i) * 132 + f];
#pragma unroll
        for (int j = 0; j < 8; j++) br[j] = W2s[f * 129 + tx * 8 + j];
#pragma unroll
        for (int i = 0; i < 4; i++)
#pragma unroll
            for (int j = 0; j < 8; j++) a3[i][j] += ar[i] * br[j];
    }

    // out[b, d*8+h, t] = relu(y2 + b2) + x[b, d*8+h, t]
#pragma unroll
    for (int j = 0; j < 8; j++) {
        int d = tx * 8 + j;
        int cch = d * 8 + h;
        long base = ((long)b * 1024 + cch) * 1024 + t0 + ty * 4;
        float bb = __ldg(&b2[d]);
        float4 xv = *(const float4*)&x[base];
        float4 ov;
        ov.x = fmaxf(a3[0][j] + bb, 0.f) + xv.x;
        ov.y = fmaxf(a3[1][j] + bb, 0.f) + xv.y;
        ov.z = fmaxf(a3[2][j] + bb, 0.f) + xv.z;
        ov.w = fmaxf(a3[3][j] + bb, 0.f) + xv.w;
        *(float4*)&out[base] = ov;
    }
}

// ---------------------------------------------------------------------------
extern "C" void kernel_launch(void* const* d_in, const int* in_sizes, int n_in,
                              void* d_out, int out_size)
{
    (void)in_sizes; (void)n_in; (void)out_size;
    const float* x     = (const float*)d_in[0];
    const float* Wq    = (const float*)d_in[1];
    const float* bq    = (const float*)d_in[2];
    const float* Wk    = (const float*)d_in[3];
    const float* bk    = (const float*)d_in[4];
    const float* Wv    = (const float*)d_in[5];
    const float* bv    = (const float*)d_in[6];
    const float* gamma = (const float*)d_in[7];
    const float* W1    = (const float*)d_in[8];
    const float* b1    = (const float*)d_in[9];
    const float* W2    = (const float*)d_in[10];
    const float* b2    = (const float*)d_in[11];
    float* out = (float*)d_out;

    float *pW1v, *pc1, *pq, *pk, *pu, *pxw1;
    cudaGetSymbolAddress((void**)&pW1v, g_W1v);
    cudaGetSymbolAddress((void**)&pc1,  g_c1);
    cudaGetSymbolAddress((void**)&pq,   g_q);
    cudaGetSymbolAddress((void**)&pk,   g_k);
    cudaGetSymbolAddress((void**)&pu,   g_u);
    cudaGetSymbolAddress((void**)&pxw1, g_xw1);

    cudaFuncSetAttribute(attn_fused, cudaFuncAttributeMaxDynamicSharedMemorySize, SMEM_BYTES);

    dim3 blk(256);
    // W1v[h] = W1 @ Wv[h]
    sgemm128<<<dim3(8, 1, 8),  blk>>>(W1, 0, Wv, (long)C_DIM * C_DIM, 1, pW1v, nullptr);
    // c1[h] = gamma*W1@bv + b1
    c1_kernel<<<8, 128>>>(W1, bv, b1, gamma, pc1);
    // q, k, u, xw1 projections
    sgemm128<<<dim3(8, 1, 64), blk>>>(Wq,   (long)DQK  * C_DIM, x, (long)C_DIM * T_DIM, 8, pq,   bq);
    sgemm128<<<dim3(8, 1, 64), blk>>>(Wk,   (long)DQK  * C_DIM, x, (long)C_DIM * T_DIM, 8, pk,   bk);
    sgemm128<<<dim3(8, 1, 64), blk>>>(pW1v, (long)DFC1 * C_DIM, x, (long)C_DIM * T_DIM, 8, pu,   nullptr);
    sgemm128<<<dim3(8, 1, 8),  blk>>>(W1, 0,                    x, (long)C_DIM * T_DIM, 1, pxw1, nullptr);
    // fused flash attention + MLP + residual
    attn_fused<<<dim3(16, 8, 8), blk, SMEM_BYTES>>>(pq, pk, pu, pxw1, pc1, gamma, W2, b2, x, out);
}

// round 15
// speedup vs baseline: 4.4976x; 4.4690x over previous
#include <cuda_runtime.h>
#include <cstdint>

// ---------------------------------------------------------------------------
// Scratch (device globals: allocation-free rule)
// ---------------------------------------------------------------------------
__device__ float g_W1v[8 * 128 * 1024];      // W1@Wv[h]  (tf32-rounded)
__device__ float g_c1 [8 * 128];             // gamma*W1@bv + b1 (fp32)
__device__ float g_q  [64 * 1024 * 128];     // [bh][t][c]  transposed, tf32
__device__ float g_k  [64 * 128 * 1024];     // [bh][c][t]  tf32
__device__ float g_u  [64 * 1024 * 128];     // [bh][t][f]  transposed, tf32
__device__ float g_xw1[8 * 1024 * 128];      // [b][t][f]   transposed, fp32
__device__ float g_xt [8 * 1024 * 1024];     // x rounded to tf32
__device__ float g_wq [8 * 128 * 1024];
__device__ float g_wk [8 * 128 * 1024];
__device__ float g_wv [8 * 1024 * 1024];
__device__ float g_w1 [128 * 1024];

// ---------------------------------------------------------------------------
// Helpers
// ---------------------------------------------------------------------------
__device__ __forceinline__ float f2tf(float f) {
    unsigned r; asm("cvt.rna.tf32.f32 %0, %1;" : "=r"(r) : "f"(f));
    return __uint_as_float(r);
}
__device__ __forceinline__ void mma8(float* d, const float* a, const float* b) {
    asm volatile(
        "mma.sync.aligned.m16n8k8.row.col.f32.tf32.tf32.f32 "
        "{%0,%1,%2,%3},{%4,%5,%6,%7},{%8,%9},{%0,%1,%2,%3};\n"
        : "+f"(d[0]), "+f"(d[1]), "+f"(d[2]), "+f"(d[3])
        : "r"(__float_as_uint(a[0])), "r"(__float_as_uint(a[1])),
          "r"(__float_as_uint(a[2])), "r"(__float_as_uint(a[3])),
          "r"(__float_as_uint(b[0])), "r"(__float_as_uint(b[1])));
}
__device__ __forceinline__ void cpa16(uint32_t dst, const float* src) {
    asm volatile("cp.async.ca.shared.global [%0], [%1], 16;" :: "r"(dst), "l"(src));
}
__device__ __forceinline__ void cp_commit() { asm volatile("cp.async.commit_group;"); }
__device__ __forceinline__ void cp_wait0()  { asm volatile("cp.async.wait_group 0;"); }
__device__ __forceinline__ void cp_wait1()  { asm volatile("cp.async.wait_group 1;"); }

// ---------------------------------------------------------------------------
// RNA tf32 rounding copy
// ---------------------------------------------------------------------------
__global__ void cvt_copy(const float* __restrict__ s, float* __restrict__ d, int n4) {
    int i = blockIdx.x * blockDim.x + threadIdx.x;
    if (i < n4) {
        float4 v = ((const float4*)s)[i];
        v.x = f2tf(v.x); v.y = f2tf(v.y); v.z = f2tf(v.z); v.w = f2tf(v.w);
        ((float4*)d)[i] = v;
    }
}

// ---------------------------------------------------------------------------
// tf32 MMA GEMM: C[z](128x1024) = A(128x1024) x B[z](1024x1024)
//   A offset sA*(z&7), B offset sB*(z/bdiv). flags: 1=transpose out, 2=round out
// 256 threads (8 warps as 2x4), warp tile 64x32, BK=16, cp.async 2-stage.
// smem: As[2][128*20] @0, Bs[2][16*136] @5120 floats (37888 B total)
// ---------------------------------------------------------------------------
__global__ __launch_bounds__(256) void gemm_mma(
    const float* __restrict__ A, long sA,
    const float* __restrict__ B, long sB, int bdiv,
    float* __restrict__ Cmat, const float* __restrict__ bias, int flags)
{
    extern __shared__ float sm[];
    uint32_t smb = (uint32_t)__cvta_generic_to_shared(sm);

    int z = blockIdx.z;
    const float* Ab = A + sA * (long)(z & 7);
    const float* Bb = B + sB * (long)(z / bdiv);
    int colBase = blockIdx.x * 128;
    int tid = threadIdx.x, lane = tid & 31, wid = tid >> 5;
    int g = lane >> 2, tg = lane & 3;
    int wm = wid & 1, wn = wid >> 1;

    float acc[4][4][4];
#pragma unroll
    for (int i = 0; i < 4; i++)
#pragma unroll
        for (int j = 0; j < 4; j++)
#pragma unroll
            for (int e = 0; e < 4; e++) acc[i][j][e] = 0.f;

    auto issue = [&](int k0, int buf) {
        uint32_t ab = smb + (unsigned)(buf * 2560) * 4u;
        uint32_t bb = smb + (unsigned)(5120 + buf * 2176) * 4u;
#pragma unroll
        for (int r = 0; r < 2; r++) {
            int slot = tid + r * 256;
            int m = slot >> 2, kq = slot & 3;
            cpa16(ab + (unsigned)(m * 20 + kq * 4) * 4u, Ab + m * 1024 + k0 + kq * 4);
        }
#pragma unroll
        for (int r = 0; r < 2; r++) {
            int slot = tid + r * 256;
            int kk = slot >> 5, n4 = slot & 31;
            cpa16(bb + (unsigned)(kk * 136 + n4 * 4) * 4u,
                  Bb + (long)(k0 + kk) * 1024 + colBase + n4 * 4);
        }
    };

    issue(0, 0);  cp_commit();
    issue(16, 1); cp_commit();

    for (int it = 0; it < 64; it++) {
        if (it == 63) cp_wait0(); else cp_wait1();
        __syncthreads();
        int buf = it & 1;
        const float* As = sm + buf * 2560;
        const float* Bs = sm + 5120 + buf * 2176;

#pragma unroll
        for (int kc = 0; kc < 2; kc++) {
            float a[4][4], bf[4][2];
#pragma unroll
            for (int mt = 0; mt < 4; mt++) {
                int base = (wm * 64 + mt * 16 + g) * 20 + kc * 8 + tg;
                a[mt][0] = As[base];            a[mt][1] = As[base + 160];
                a[mt][2] = As[base + 4];        a[mt][3] = As[base + 164];
            }
#pragma unroll
            for (int nt = 0; nt < 4; nt++) {
                int bo = (kc * 8 + tg) * 136 + wn * 32 + nt * 8 + g;
                bf[nt][0] = Bs[bo];             bf[nt][1] = Bs[bo + 544];
            }
#pragma unroll
            for (int mt = 0; mt < 4; mt++)
#pragma unroll
                for (int nt = 0; nt < 4; nt++) mma8(acc[mt][nt], a[mt], bf[nt]);
        }
        __syncthreads();
        if (it < 62) { issue((it + 2) * 16, buf); cp_commit(); }
    }

    const float* biasb = bias ? bias + (z & 7) * 128 : nullptr;
    float* Cb = Cmat + (long)z * 131072;
    bool tr = (flags & 1), rnd = (flags & 2);
#pragma unroll
    for (int mt = 0; mt < 4; mt++) {
        int m = wm * 64 + mt * 16;
        float b0 = biasb ? biasb[m + g] : 0.f;
        float b1 = biasb ? biasb[m + g + 8] : 0.f;
#pragma unroll
        for (int nt = 0; nt < 4; nt++) {
            int n = colBase + wn * 32 + nt * 8 + 2 * tg;
            float v0 = acc[mt][nt][0] + b0, v1 = acc[mt][nt][1] + b0;
            float v2 = acc[mt][nt][2] + b1, v3 = acc[mt][nt][3] + b1;
            if (rnd) { v0 = f2tf(v0); v1 = f2tf(v1); v2 = f2tf(v2); v3 = f2tf(v3); }
            if (!tr) {
                *(float2*)&Cb[(m + g) * 1024 + n]     = make_float2(v0, v1);
                *(float2*)&Cb[(m + g + 8) * 1024 + n] = make_float2(v2, v3);
            } else {
                Cb[(long)n * 128 + m + g]           = v0;
                Cb[(long)(n + 1) * 128 + m + g]     = v1;
                Cb[(long)n * 128 + m + g + 8]       = v2;
                Cb[(long)(n + 1) * 128 + m + g + 8] = v3;
            }
        }
    }
}

// ---------------------------------------------------------------------------
// c1[h][f] = gamma[h] * sum_c W1[f][c]*bv[h][c] + b1[f]   (fp32, tiny)
// ---------------------------------------------------------------------------
__global__ void c1_kernel(const float* __restrict__ W1, const float* __restrict__ bv,
                          const float* __restrict__ b1, const float* __restrict__ gamma,
                          float* __restrict__ c1)
{
    int h = blockIdx.x, f = threadIdx.x;
    const float* bvh = bv + h * 1024;
    float s = 0.f;
    for (int c = 0; c < 1024; c++) s += W1[f * 1024 + c] * bvh[c];
    c1[h * 128 + f] = gamma[h] * s + b1[f];
}

// ---------------------------------------------------------------------------
// Fused tf32-MMA flash attention + FC1 + FC2 + residual + permute.
// Block: 512 threads (16 warps), 128 queries, s-chunks of 64, grid (8,8,8).
// smem floats: Qs@0[128x132] Ks@16896[128x72] Us@26112[64x136]
//              Ss@34816[128x68] m@43520 l@43648 f@43776  (total 43904)
// Epilogue aliases: y1s=Qs, W2s@16896[128x132]
// ---------------------------------------------------------------------------
#define ATT_SMEM (43904 * 4)

__global__ __launch_bounds__(512) void attn_mma(
    const float* __restrict__ qg, const float* __restrict__ kg,
    const float* __restrict__ ug, const float* __restrict__ xw1t,
    const float* __restrict__ c1, const float* __restrict__ gamma,
    const float* __restrict__ W2, const float* __restrict__ b2,
    const float* __restrict__ x,  float* __restrict__ out)
{
    extern __shared__ float sm[];
    float* Qs   = sm;
    float* Ks   = sm + 16896;
    float* Us   = sm + 26112;
    float* Ss   = sm + 34816;
    float* m_sm = sm + 43520;
    float* l_sm = sm + 43648;
    float* f_sm = sm + 43776;
    float* y1s  = sm;           // alias Qs
    float* W2s  = sm + 16896;   // alias Ks/Us
    uint32_t smb = (uint32_t)__cvta_generic_to_shared(sm);

    int tid = threadIdx.x, lane = tid & 31, wid = tid >> 5;
    int g = lane >> 2, tg = lane & 3;
    int qt = blockIdx.x, h = blockIdx.y, b = blockIdx.z;
    int t0 = qt * 128, bh = b * 8 + h;

    const float* qb = qg + (long)bh * 131072;   // [t][c]
    const float* kb = kg + (long)bh * 131072;   // [c][t]
    const float* ub = ug + (long)bh * 131072;   // [t][f]

    int qw = (wid & 7) * 16;       // GEMM1/2 warp q-base
    int sw = (wid >> 3) * 32;      // GEMM1 warp s-base
    int fw = (wid >> 3) * 64;      // GEMM2 warp f-base

    auto issueK = [&](int ci) {
        int s0 = ci * 64;
#pragma unroll
        for (int r = 0; r < 4; r++) {
            int i = tid + r * 512;
            int c = i >> 4, s4 = i & 15;
            cpa16(smb + (unsigned)(16896 + c * 72 + s4 * 4) * 4u,
                  kb + c * 1024 + s0 + s4 * 4);
        }
    };
    auto issueU = [&](int ci) {
        int s0 = ci * 64;
#pragma unroll
        for (int r = 0; r < 4; r++) {
            int i = tid + r * 512;
            int s = i >> 5, f4 = i & 31;
            cpa16(smb + (unsigned)(26112 + s * 136 + f4 * 4) * 4u,
                  ub + (long)(s0 + s) * 128 + f4 * 4);
        }
    };

    // prologue: Q tile + chunk 0
#pragma unroll
    for (int r = 0; r < 8; r++) {
        int i = tid + r * 512;
        int q = i >> 5, c4 = i & 31;
        cpa16(smb + (unsigned)(q * 132 + c4 * 4) * 4u,
              qb + (long)(t0 + q) * 128 + c4 * 4);
    }
    issueK(0); issueU(0); cp_commit();
    if (tid < 128) { m_sm[tid] = -1e30f; l_sm[tid] = 0.f; }
    cp_wait0();
    __syncthreads();

    float acc2[8][4];
#pragma unroll
    for (int n = 0; n < 8; n++)
#pragma unroll
        for (int e = 0; e < 4; e++) acc2[n][e] = 0.f;

    for (int ci = 0; ci < 16; ci++) {
        // ---- GEMM1: S[128q x 64s] = Q x K ----
        float acc1[4][4];
#pragma unroll
        for (int n = 0; n < 4; n++)
#pragma unroll
            for (int e = 0; e < 4; e++) acc1[n][e] = 0.f;
#pragma unroll
        for (int kc = 0; kc < 16; kc++) {
            float a[4];
            int base = (qw + g) * 132 + kc * 8 + tg;
            a[0] = Qs[base];            a[1] = Qs[base + 1056];
            a[2] = Qs[base + 4];        a[3] = Qs[base + 1060];
#pragma unroll
            for (int n = 0; n < 4; n++) {
                float bf[2];
                int bo = (kc * 8 + tg) * 72 + sw + n * 8 + g;
                bf[0] = Ks[bo]; bf[1] = Ks[bo + 288];
                mma8(acc1[n], a, bf);
            }
        }
#pragma unroll
        for (int n = 0; n < 4; n++) {
            int s = sw + n * 8 + 2 * tg;
            *(float2*)&Ss[(qw + g) * 68 + s]     = make_float2(acc1[n][0], acc1[n][1]);
            *(float2*)&Ss[(qw + g + 8) * 68 + s] = make_float2(acc1[n][2], acc1[n][3]);
        }
        __syncthreads();
        if (ci < 15) { issueK(ci + 1); cp_commit(); }

        // ---- softmax (4 lanes per row, 16 s each) ----
        {
            int row = tid >> 2, seg = tid & 3;
            float* srow = &Ss[row * 68 + seg * 16];
            float mx = -1e30f;
#pragma unroll
            for (int j = 0; j < 16; j++) mx = fmaxf(mx, srow[j]);
            mx = fmaxf(mx, __shfl_xor_sync(0xffffffffu, mx, 1));
            mx = fmaxf(mx, __shfl_xor_sync(0xffffffffu, mx, 2));
            float mo = m_sm[row];
            float mn = fmaxf(mo, mx);
            float fr = __expf(mo - mn);
            float sum = 0.f;
#pragma unroll
            for (int j = 0; j < 16; j++) {
                float p = f2tf(__expf(srow[j] - mn));
                srow[j] = p;
                sum += p;
            }
            sum += __shfl_xor_sync(0xffffffffu, sum, 1);
            sum += __shfl_xor_sync(0xffffffffu, sum, 2);
            if (seg == 0) {
                m_sm[row] = mn;
                f_sm[row] = fr;
                l_sm[row] = l_sm[row] * fr + sum;
            }
        }
        __syncthreads();

        // ---- rescale + GEMM2: acc2[128q x 128f] += P x U ----
        {
            float f0 = f_sm[qw + g], f1 = f_sm[qw + g + 8];
#pragma unroll
            for (int n = 0; n < 8; n++) {
                acc2[n][0] *= f0; acc2[n][1] *= f0;
                acc2[n][2] *= f1; acc2[n][3] *= f1;
            }
        }
#pragma unroll
        for (int kc = 0; kc < 8; kc++) {
            float a[4];
            int base = (qw + g) * 68 + kc * 8 + tg;
            a[0] = Ss[base];            a[1] = Ss[base + 544];
            a[2] = Ss[base + 4];        a[3] = Ss[base + 548];
#pragma unroll
            for (int n = 0; n < 8; n++) {
                float bf[2];
                int bo = (kc * 8 + tg) * 136 + fw + n * 8 + g;
                bf[0] = Us[bo]; bf[1] = Us[bo + 544];
                mma8(acc2[n], a, bf);
            }
        }
        __syncthreads();
        if (ci < 15) { issueU(ci + 1); cp_commit(); cp_wait0(); }
        __syncthreads();
    }

    // ---- epilogue: y1 = relu(gamma*z + xw1 + c1) -> smem (tf32) ----
    {
        float li0 = 1.f / l_sm[qw + g], li1 = 1.f / l_sm[qw + g + 8];
        float gam = __ldg(&gamma[h]);
#pragma unroll
        for (int n = 0; n < 8; n++) {
            int f = fw + n * 8 + 2 * tg;
            float2 cv = *(const float2*)&c1[h * 128 + f];
            float2 xa = *(const float2*)&xw1t[(long)(b * 1024 + t0 + qw + g) * 128 + f];
            float2 xb = *(const float2*)&xw1t[(long)(b * 1024 + t0 + qw + g + 8) * 128 + f];
            float y0 = f2tf(fmaxf(gam * acc2[n][0] * li0 + xa.x + cv.x, 0.f));
            float y1 = f2tf(fmaxf(gam * acc2[n][1] * li0 + xa.y + cv.y, 0.f));
            float y2 = f2tf(fmaxf(gam * acc2[n][2] * li1 + xb.x + cv.x, 0.f));
            float y3 = f2tf(fmaxf(gam * acc2[n][3] * li1 + xb.y + cv.y, 0.f));
            *(float2*)&y1s[(qw + g) * 132 + f]     = make_float2(y0, y1);
            *(float2*)&y1s[(qw + g + 8) * 132 + f] = make_float2(y2, y3);
        }
    }
    // W2 -> smem (row-major [d][f], rounded)
#pragma unroll
    for (int r = 0; r < 8; r++) {
        int i = tid + r * 512;
        int d = i >> 5, f4 = i & 31;
        float4 w = *(const float4*)&W2[d * 128 + f4 * 4];
        w.x = f2tf(w.x); w.y = f2tf(w.y); w.z = f2tf(w.z); w.w = f2tf(w.w);
        *(float4*)&W2s[d * 132 + f4 * 4] = w;
    }
    __syncthreads();

    // ---- GEMM3 (transposed): D'[128d x 128q] = W2 x y1^T ----
    int dw = (wid & 7) * 16, qw3 = (wid >> 3) * 64;
    float acc3[8][4];
#pragma unroll
    for (int n = 0; n < 8; n++)
#pragma unroll
        for (int e = 0; e < 4; e++) acc3[n][e] = 0.f;
#pragma unroll
    for (int kc = 0; kc < 16; kc++) {
        float a[4];
        int base = (dw + g) * 132 + kc * 8 + tg;
        a[0] = W2s[base];           a[1] = W2s[base + 1056];
        a[2] = W2s[base + 4];       a[3] = W2s[base + 1060];
#pragma unroll
        for (int n = 0; n < 8; n++) {
            float bf[2];
            int bo = (qw3 + n * 8 + g) * 132 + kc * 8 + tg;
            bf[0] = y1s[bo]; bf[1] = y1s[bo + 4];
            mma8(acc3[n], a, bf);
        }
    }

    // ---- out[b, d*8+h, t] = relu(y2 + b2) + x ----
#pragma unroll
    for (int n = 0; n < 8; n++) {
        int q = qw3 + n * 8 + 2 * tg;
        int d0 = dw + g, d1 = dw + g + 8;
        float bb0 = __ldg(&b2[d0]), bb1 = __ldg(&b2[d1]);
        long a0 = ((long)b * 1024 + d0 * 8 + h) * 1024 + t0 + q;
        long a1 = ((long)b * 1024 + d1 * 8 + h) * 1024 + t0 + q;
        float2 x0 = *(const float2*)&x[a0];
        float2 x1 = *(const float2*)&x[a1];
        float2 o0 = make_float2(fmaxf(acc3[n][0] + bb0, 0.f) + x0.x,
                                fmaxf(acc3[n][1] + bb0, 0.f) + x0.y);
        float2 o1 = make_float2(fmaxf(acc3[n][2] + bb1, 0.f) + x1.x,
                                fmaxf(acc3[n][3] + bb1, 0.f) + x1.y);
        *(float2*)&out[a0] = o0;
        *(float2*)&out[a1] = o1;
    }
}

// ---------------------------------------------------------------------------
extern "C" void kernel_launch(void* const* d_in, const int* in_sizes, int n_in,
                              void* d_out, int out_size)
{
    (void)in_sizes; (void)n_in; (void)out_size;
    const float* x     = (const float*)d_in[0];
    const float* Wq    = (const float*)d_in[1];
    const float* bq    = (const float*)d_in[2];
    const float* Wk    = (const float*)d_in[3];
    const float* bk    = (const float*)d_in[4];
    const float* Wv    = (const float*)d_in[5];
    const float* bv    = (const float*)d_in[6];
    const float* gamma = (const float*)d_in[7];
    const float* W1    = (const float*)d_in[8];
    const float* b1    = (const float*)d_in[9];
    const float* W2    = (const float*)d_in[10];
    const float* b2    = (const float*)d_in[11];
    float* out = (float*)d_out;

    float *pW1v, *pc1, *pq, *pk, *pu, *pxw1, *pxt, *pwq, *pwk, *pwv, *pw1;
    cudaGetSymbolAddress((void**)&pW1v, g_W1v);
    cudaGetSymbolAddress((void**)&pc1,  g_c1);
    cudaGetSymbolAddress((void**)&pq,   g_q);
    cudaGetSymbolAddress((void**)&pk,   g_k);
    cudaGetSymbolAddress((void**)&pu,   g_u);
    cudaGetSymbolAddress((void**)&pxw1, g_xw1);
    cudaGetSymbolAddress((void**)&pxt,  g_xt);
    cudaGetSymbolAddress((void**)&pwq,  g_wq);
    cudaGetSymbolAddress((void**)&pwk,  g_wk);
    cudaGetSymbolAddress((void**)&pwv,  g_wv);
    cudaGetSymbolAddress((void**)&pw1,  g_w1);

    cudaFuncSetAttribute(attn_mma, cudaFuncAttributeMaxDynamicSharedMemorySize, ATT_SMEM);

    // tf32 RNA pre-rounding
    cvt_copy<<<8192, 256>>>(x,  pxt, 2097152);
    cvt_copy<<<1024, 256>>>(Wq, pwq, 262144);
    cvt_copy<<<1024, 256>>>(Wk, pwk, 262144);
    cvt_copy<<<8192, 256>>>(Wv, pwv, 2097152);
    cvt_copy<<<128,  256>>>(W1, pw1, 32768);

    dim3 blk(256);
    int GSM = 9472 * 4;
    // W1v[h] = W1 @ Wv[h]   (rounded out)
    gemm_mma<<<dim3(8, 1, 8),  blk, GSM>>>(pw1, 0, pwv, 1048576L, 1, pW1v, nullptr, 2);
    c1_kernel<<<8, 128>>>(W1, bv, b1, gamma, pc1);
    // q: transposed + rounded, bias bq
    gemm_mma<<<dim3(8, 1, 64), blk, GSM>>>(pwq, 131072L, pxt, 1048576L, 8, pq,   bq, 3);
    // k: rounded, bias bk
    gemm_mma<<<dim3(8, 1, 64), blk, GSM>>>(pwk, 131072L, pxt, 1048576L, 8, pk,   bk, 2);
    // u: transposed + rounded
    gemm_mma<<<dim3(8, 1, 64), blk, GSM>>>(pW1v, 131072L, pxt, 1048576L, 8, pu,  nullptr, 3);
    // xw1: transposed, fp32 out
    gemm_mma<<<dim3(8, 1, 8),  blk, GSM>>>(pw1, 0, pxt, 1048576L, 1, pxw1, nullptr, 1);
    // fused attention + MLP + residual
    attn_mma<<<dim3(8, 8, 8), 512, ATT_SMEM>>>(pq, pk, pu, pxw1, pc1, gamma, W2, b2, x, out);
}